// round 10
// baseline (speedup 1.0000x reference)
#include <cuda_runtime.h>
#include <cuda_bf16.h>

#define N_COLS 2048                 // hidden dim
#define VECS_PER_ROW (N_COLS / 4)   // 512 float4
#define THREADS 128                 // 4 float4 per thread, 1 row per CTA
#define NWARPS (THREADS / 32)       // 4
#define EPS 1e-5f

__global__ __launch_bounds__(THREADS)
void rmsnorm_kernel(const float4* __restrict__ x,
                    const float4* __restrict__ g,
                    float4* __restrict__ out)
{
    const int row = blockIdx.x;
    const float4* xr = x + (size_t)row * VECS_PER_ROW;
    float4* outr = out + (size_t)row * VECS_PER_ROW;

    const int t = threadIdx.x;
    const int warp = t >> 5;
    const int lane = t & 31;

    // x has zero reuse within a launch: bypass L1 fill (L2-only).
    // 4 front-batched independent LDG.128 per thread (MLP=4).
    float4 v0 = __ldcg(&xr[t]);
    float4 v1 = __ldcg(&xr[t + THREADS]);
    float4 v2 = __ldcg(&xr[t + 2 * THREADS]);
    float4 v3 = __ldcg(&xr[t + 3 * THREADS]);

    // Sum of squares, independent chains.
    float a0 = v0.x * v0.x + v0.y * v0.y + v0.z * v0.z + v0.w * v0.w;
    float a1 = v1.x * v1.x + v1.y * v1.y + v1.z * v1.z + v1.w * v1.w;
    float a2 = v2.x * v2.x + v2.y * v2.y + v2.z * v2.z + v2.w * v2.w;
    float a3 = v3.x * v3.x + v3.y * v3.y + v3.z * v3.z + v3.w * v3.w;
    float ss = (a0 + a1) + (a2 + a3);

    // Warp reduce (redux.sync.add.f32 unsupported on sm_103).
    #pragma unroll
    for (int off = 16; off > 0; off >>= 1)
        ss += __shfl_xor_sync(0xFFFFFFFFu, ss, off);

    // Single-barrier block reduce over 4 warp partials.
    __shared__ float warp_sums[NWARPS];
    if (lane == 0) warp_sums[warp] = ss;
    __syncthreads();

    float total = (warp_sums[0] + warp_sums[1]) + (warp_sums[2] + warp_sums[3]);

    const float scale = rsqrtf(total * (1.0f / (float)N_COLS) + EPS);

    // g: 8 KB, L1/L2-resident broadcast.
    float4 g0 = g[t];
    float4 g1 = g[t + THREADS];
    float4 g2 = g[t + 2 * THREADS];
    float4 g3 = g[t + 3 * THREADS];

    float4 o0, o1, o2, o3;
    o0.x = v0.x * scale * g0.x;  o0.y = v0.y * scale * g0.y;
    o0.z = v0.z * scale * g0.z;  o0.w = v0.w * scale * g0.w;
    o1.x = v1.x * scale * g1.x;  o1.y = v1.y * scale * g1.y;
    o1.z = v1.z * scale * g1.z;  o1.w = v1.w * scale * g1.w;
    o2.x = v2.x * scale * g2.x;  o2.y = v2.y * scale * g2.y;
    o2.z = v2.z * scale * g2.z;  o2.w = v2.w * scale * g2.w;
    o3.x = v3.x * scale * g3.x;  o3.y = v3.y * scale * g3.y;
    o3.z = v3.z * scale * g3.z;  o3.w = v3.w * scale * g3.w;

    outr[t] = o0;
    outr[t + THREADS] = o1;
    outr[t + 2 * THREADS] = o2;
    outr[t + 3 * THREADS] = o3;
}

extern "C" void kernel_launch(void* const* d_in, const int* in_sizes, int n_in,
                              void* d_out, int out_size)
{
    const float4* x = (const float4*)d_in[0];
    const float4* g = (const float4*)d_in[1];
    float4* out = (float4*)d_out;

    const int n_rows = in_sizes[0] / N_COLS;  // 16384

    rmsnorm_kernel<<<n_rows, THREADS>>>(x, g, out);
}